// round 4
// baseline (speedup 1.0000x reference)
#include <cuda_runtime.h>

#define OC_N       32
#define TPO        144            // tables per output channel
#define IC_N       16
#define PH         34
#define PW         34
#define CH_STRIDE  (PH*PW)        // 1156
#define TILE_ELEMS (IC_N*CH_STRIDE)   // 18496 floats = 73984 B
#define NTHREADS   512
#define S          (8*PW)         // 272: stride between position groups

// Block = (batch, oc-pair, image-half). 512 threads = 2 x 256 (one oc each),
// sharing ONE padded-image tile in shared memory. Each thread: 2 positions,
// 144 tables, 2 LDS + 3 FMA per eval.
extern __shared__ float smem[];

__global__ void __launch_bounds__(NTHREADS, 2)
lutconv_fused(const float*  __restrict__ inp,
              const float4* __restrict__ w4,
              const int*    __restrict__ mc,
              const int*    __restrict__ mkh,
              const int*    __restrict__ mkw,
              float*        __restrict__ out) {
    const int bid = blockIdx.x;
    const int b   = bid >> 5;          // batch
    const int q   = bid & 31;
    const int ocp = q >> 1;            // oc pair index (0..15)
    const int h   = q & 1;             // image half (rows 0-15 / 16-31)
    const int tid = threadIdx.x;
    const int wg  = tid >> 8;          // which oc of the pair
    const int ttid = tid & 255;
    const int oc  = ocp*2 + wg;

    float*  tile  = smem;                               // [TILE_ELEMS]
    float4* scoef = (float4*)(smem + TILE_ELEMS);       // [2][TPO]
    float*  scw   = (float*)(scoef + 2*TPO);            // [2][TPO]
    float*  sA    = scw + 2*TPO;                        // [2]

    // --- Per-table precompute for BOTH ocs (288 tables)
    if (tid < 2*TPO) {
        const int loc = tid;                            // [0,288)
        const int oci = loc >= TPO;
        const int t   = (ocp*2 + oci)*TPO + (loc - oci*TPO);
        const float4 wv = w4[t];
        const float bco = 0.25f * (-wv.x + wv.y - wv.z + wv.w);
        const float cco = 0.25f * (-wv.x - wv.y + wv.z + wv.w);
        const float dco = 0.25f * ( wv.x - wv.y - wv.z + wv.w);
        const float aco = 0.25f * ( wv.x + wv.y + wv.z + wv.w);
        const int m0 = 2*t;
        const unsigned off0 = (unsigned)(mc[m0  ]*CH_STRIDE + mkh[m0  ]*PW + mkw[m0  ]);
        const unsigned off1 = (unsigned)(mc[m0+1]*CH_STRIDE + mkh[m0+1]*PW + mkw[m0+1]);
        float4 p;
        p.x = __uint_as_float(off0 | (off1 << 16));
        p.y = bco; p.z = cco; p.w = dco;
        scoef[loc] = p;
        scw[loc]   = aco;
    }

    // --- Stage padded tile (512 threads): vector zero-fill + float4 interior
    {
        const float4 z4 = make_float4(0.f, 0.f, 0.f, 0.f);
        float4* t4 = (float4*)tile;
        #pragma unroll
        for (int i = tid; i < TILE_ELEMS/4; i += NTHREADS) t4[i] = z4;
    }
    __syncthreads();
    {
        const float4* ib4 = (const float4*)(inp + (size_t)b * (IC_N*32*32));
        #pragma unroll
        for (int i = tid; i < 4096; i += NTHREADS) {    // 8 iterations
            const float4 v = ib4[i];
            const int j = i << 2;
            const int c = j >> 10;
            const int y = (j >> 5) & 31;
            const int x = j & 31;
            float* dst = tile + c*CH_STRIDE + (y+1)*PW + x + 1;
            dst[0] = v.x; dst[1] = v.y; dst[2] = v.z; dst[3] = v.w;
        }
    }
    __syncthreads();

    // --- Per-oc constant: warp 0 reduces oc0's 144 constants, warp 8 oc1's
    if (ttid < 32) {
        const float* w_ = scw + wg*TPO;
        float s = w_[ttid] + w_[ttid+32] + w_[ttid+64] + w_[ttid+96]
                + (ttid < (TPO - 128) ? w_[ttid+128] : 0.0f);
        #pragma unroll
        for (int d = 16; d; d >>= 1) s += __shfl_xor_sync(0xffffffffu, s, d);
        if (ttid == 0) sA[wg] = s;
    }
    __syncthreads();

    // --- Main loop: this thread's 2 positions: y = h*16 + p*8 + ttid/32
    float acc0 = 0.f, acc1 = 0.f;
    const float* base = tile + (h*16 + (ttid >> 5))*PW + (ttid & 31);
    const float4* cf = scoef + wg*TPO;

    #pragma unroll 2
    for (int t = 0; t < TPO; t += 2) {
        const float4 pa = cf[t];
        const float4 pb = cf[t+1];
        const unsigned ua = __float_as_uint(pa.x);
        const unsigned ub = __float_as_uint(pb.x);
        const float* A0 = base + (ua & 0xffffu);
        const float* A1 = base + (ua >> 16);
        const float* B0 = base + (ub & 0xffffu);
        const float* B1 = base + (ub >> 16);

        const float xa00 = A0[0], xa10 = A1[0];
        const float xa01 = A0[S], xa11 = A1[S];
        const float xb00 = B0[0], xb10 = B1[0];
        const float xb01 = B0[S], xb11 = B1[S];

        acc0 = fmaf(xa00, fmaf(pa.w, xa10, pa.y), fmaf(pa.z, xa10, acc0));
        acc1 = fmaf(xa01, fmaf(pa.w, xa11, pa.y), fmaf(pa.z, xa11, acc1));
        acc0 = fmaf(xb00, fmaf(pb.w, xb10, pb.y), fmaf(pb.z, xb10, acc0));
        acc1 = fmaf(xb01, fmaf(pb.w, xb11, pb.y), fmaf(pb.z, xb11, acc1));
    }

    const float A = sA[wg];
    float* ob = out + ((size_t)(b*OC_N + oc)) * 1024 + h*512;
    ob[ttid      ] = acc0 + A;
    ob[ttid + 256] = acc1 + A;
}

// ---------------------------------------------------------------------------
extern "C" void kernel_launch(void* const* d_in, const int* in_sizes, int n_in,
                              void* d_out, int out_size) {
    const float*  inp = (const float*)d_in[0];
    const float4* w4  = (const float4*)d_in[1];
    const int*    mc  = (const int*)d_in[2];
    const int*    mkh = (const int*)d_in[3];
    const int*    mkw = (const int*)d_in[4];
    float*        out = (float*)d_out;

    const int smem_bytes = TILE_ELEMS*(int)sizeof(float)
                         + 2*TPO*(int)sizeof(float4)
                         + 2*TPO*(int)sizeof(float)
                         + 2*(int)sizeof(float);       // 79752 B
    cudaFuncSetAttribute(lutconv_fused,
                         cudaFuncAttributeMaxDynamicSharedMemorySize, smem_bytes);
    lutconv_fused<<<256, NTHREADS, smem_bytes>>>(inp, w4, mc, mkh, mkw, out);
}